// round 1
// baseline (speedup 1.0000x reference)
#include <cuda_runtime.h>
#include <cstddef>

// Problem constants (fixed by the reference)
#define N_U   8192
#define N_I   8192
#define D_IN  2048
#define D_H   2048
#define N_TOT (N_U + N_I)

// Scratch for the intermediate `support` matrix (16384 x 2048 fp32, 128 MB).
__device__ float g_support[(size_t)N_TOT * D_H];

#define BM 128
#define BN 128
#define BK 16

// Generic tiled SGEMM:
//   C[m,n] = epilogue( sum_k A(m,k) * B(k,n) )
// A(m,k) = A_K_CONTIG ? A[m*lda + k] : A[k*lda + m]
// B(k,n) = B_N_CONTIG ? B[k*ldb + n] : B[n*ldb + k]
// EPI==0: C += bias E[n];   EPI==1: C *= E[m]
// Requires M%128==0, N%128==0, K%16==0 (true for all three calls).
template<bool A_K_CONTIG, bool B_N_CONTIG, int EPI>
__launch_bounds__(256, 2)
__global__ void sgemm_kernel(const float* __restrict__ A,
                             const float* __restrict__ B,
                             const float* __restrict__ E,
                             float* __restrict__ C,
                             int M, int N, int K, int lda, int ldb)
{
    __shared__ float As[BK][BM];
    __shared__ float Bs[BK][BN];

    const int tid = threadIdx.x;       // 0..255
    const int m0  = blockIdx.y * BM;
    const int n0  = blockIdx.x * BN;

    const int tx = tid & 15;           // 0..15
    const int ty = tid >> 4;           // 0..15

    float acc[8][8];
#pragma unroll
    for (int i = 0; i < 8; i++)
#pragma unroll
        for (int j = 0; j < 8; j++) acc[i][j] = 0.f;

    for (int k0 = 0; k0 < K; k0 += BK) {
        // ---- load A tile into As[k][m] ----
        if (A_K_CONTIG) {
            // A[m*lda + k], k contiguous -> load float4 along k, transpose into smem
            const int row = tid >> 2;            // 0..63
            const int kg  = (tid & 3) * 4;       // 0,4,8,12
#pragma unroll
            for (int r = 0; r < 2; r++) {
                const int m = row + r * 64;
                float4 v = *reinterpret_cast<const float4*>(
                    &A[(size_t)(m0 + m) * lda + k0 + kg]);
                As[kg + 0][m] = v.x;
                As[kg + 1][m] = v.y;
                As[kg + 2][m] = v.z;
                As[kg + 3][m] = v.w;
            }
        } else {
            // A[k*lda + m], m contiguous -> directly coalesced
            const int k  = tid >> 5;             // 0..7
            const int mg = (tid & 31) * 4;       // 0..124
#pragma unroll
            for (int r = 0; r < 2; r++) {
                const int kk = k + r * 8;
                float4 v = *reinterpret_cast<const float4*>(
                    &A[(size_t)(k0 + kk) * lda + m0 + mg]);
                *reinterpret_cast<float4*>(&As[kk][mg]) = v;
            }
        }
        // ---- load B tile into Bs[k][n] ----
        if (B_N_CONTIG) {
            const int k  = tid >> 5;
            const int ng = (tid & 31) * 4;
#pragma unroll
            for (int r = 0; r < 2; r++) {
                const int kk = k + r * 8;
                float4 v = *reinterpret_cast<const float4*>(
                    &B[(size_t)(k0 + kk) * ldb + n0 + ng]);
                *reinterpret_cast<float4*>(&Bs[kk][ng]) = v;
            }
        } else {
            // B[n*ldb + k], k contiguous -> load along k, transpose into smem
            const int col = tid >> 2;            // 0..63
            const int kg  = (tid & 3) * 4;
#pragma unroll
            for (int r = 0; r < 2; r++) {
                const int n = col + r * 64;
                float4 v = *reinterpret_cast<const float4*>(
                    &B[(size_t)(n0 + n) * ldb + k0 + kg]);
                Bs[kg + 0][n] = v.x;
                Bs[kg + 1][n] = v.y;
                Bs[kg + 2][n] = v.z;
                Bs[kg + 3][n] = v.w;
            }
        }
        __syncthreads();

        // ---- compute 8x8 microtile (rows {ty*4..+3, 64+ty*4..+3},
        //      cols {tx*4..+3, 64+tx*4..+3}) ----
#pragma unroll
        for (int kk = 0; kk < BK; kk++) {
            float ar[8], br[8];
            *reinterpret_cast<float4*>(&ar[0]) =
                *reinterpret_cast<const float4*>(&As[kk][ty * 4]);
            *reinterpret_cast<float4*>(&ar[4]) =
                *reinterpret_cast<const float4*>(&As[kk][64 + ty * 4]);
            *reinterpret_cast<float4*>(&br[0]) =
                *reinterpret_cast<const float4*>(&Bs[kk][tx * 4]);
            *reinterpret_cast<float4*>(&br[4]) =
                *reinterpret_cast<const float4*>(&Bs[kk][64 + tx * 4]);
#pragma unroll
            for (int i = 0; i < 8; i++)
#pragma unroll
                for (int j = 0; j < 8; j++)
                    acc[i][j] = fmaf(ar[i], br[j], acc[i][j]);
        }
        __syncthreads();
    }

    // ---- epilogue + store ----
#pragma unroll
    for (int i = 0; i < 8; i++) {
        const int mi = (i < 4) ? (ty * 4 + i) : (64 + ty * 4 + (i - 4));
        const int m  = m0 + mi;
        float scale = 1.f;
        if (EPI == 1) scale = E[m];
#pragma unroll
        for (int jh = 0; jh < 2; jh++) {
            const int n = n0 + jh * 64 + tx * 4;
            float4 v;
            v.x = acc[i][jh * 4 + 0];
            v.y = acc[i][jh * 4 + 1];
            v.z = acc[i][jh * 4 + 2];
            v.w = acc[i][jh * 4 + 3];
            if (EPI == 0) {
                v.x += E[n + 0];
                v.y += E[n + 1];
                v.z += E[n + 2];
                v.w += E[n + 3];
            } else {
                v.x *= scale; v.y *= scale; v.z *= scale; v.w *= scale;
            }
            *reinterpret_cast<float4*>(&C[(size_t)m * N + n]) = v;
        }
    }
}

extern "C" void kernel_launch(void* const* d_in, const int* in_sizes, int n_in,
                              void* d_out, int out_size)
{
    const float* input  = (const float*)d_in[0];  // (N_TOT, D_IN)
    const float* adj    = (const float*)d_in[1];  // (N_U, N_I)
    const float* degree = (const float*)d_in[2];  // (N_TOT,)
    const float* W      = (const float*)d_in[3];  // (D_H, D_IN)
    const float* b      = (const float*)d_in[4];  // (D_H,)
    float* out = (float*)d_out;                   // (N_TOT, D_H)

    float* support = nullptr;
    cudaGetSymbolAddress((void**)&support, g_support);

    const float* sup_u = support;                       // rows [0, N_U)
    const float* sup_i = support + (size_t)N_U * D_H;   // rows [N_U, N_TOT)

    dim3 blk(256);

    // GEMM1: support = input @ W^T + b
    // A = input (K-contig, lda=D_IN); B(k,n) = W[n*D_IN + k] (K-contig -> B_N_CONTIG=false)
    {
        dim3 grid(D_H / BN, N_TOT / BM);
        sgemm_kernel<true, false, 0><<<grid, blk>>>(
            input, W, b, support, N_TOT, D_H, D_IN, D_IN, D_IN);
    }
    // GEMM2: out_u = deg_u ⊙ (adj @ sup_i)
    {
        dim3 grid(D_H / BN, N_U / BM);
        sgemm_kernel<true, true, 1><<<grid, blk>>>(
            adj, sup_i, degree, out, N_U, D_H, N_I, N_I, D_H);
    }
    // GEMM3: out_i = deg_i ⊙ (adj^T @ sup_u)
    // A(m,k) = adj[k*N_I + m] (m contiguous -> A_K_CONTIG=false, lda=N_I)
    {
        dim3 grid(D_H / BN, N_I / BM);
        sgemm_kernel<false, true, 1><<<grid, blk>>>(
            adj, sup_u, degree + N_U, out + (size_t)N_U * D_H,
            N_I, D_H, N_U, N_I, D_H);
    }
}

// round 2
// speedup vs baseline: 2.9319x; 2.9319x over previous
#include <cuda_runtime.h>
#include <cstddef>

// Problem constants (fixed by the reference)
#define N_U   8192
#define N_I   8192
#define D_IN  2048
#define D_H   2048
#define N_TOT (N_U + N_I)

// Scratch for the intermediate `support` matrix (16384 x 2048 fp32, 128 MB).
__device__ float g_support[(size_t)N_TOT * D_H];

#define BM 128
#define BN 128
#define BK 16

// smem row strides (floats), chosen so mma fragment loads are bank-conflict-free:
//  K-contiguous panels:  [rows][BK+4]   -> stride 20  (20*4B, 16B-aligned)
//  MN-contiguous panels: [BK][dim+8]    -> stride 136 (136*4B, 16B-aligned)
#define S_KC 20
#define S_MC 136

__device__ __forceinline__ void cp_async16(void* smem_ptr, const void* gmem_ptr) {
    unsigned s = (unsigned)__cvta_generic_to_shared(smem_ptr);
    asm volatile("cp.async.cg.shared.global [%0], [%1], 16;\n" :: "r"(s), "l"(gmem_ptr));
}
__device__ __forceinline__ void cp_commit() {
    asm volatile("cp.async.commit_group;\n" ::: "memory");
}
template<int N>
__device__ __forceinline__ void cp_wait() {
    asm volatile("cp.async.wait_group %0;\n" :: "n"(N) : "memory");
}
__device__ __forceinline__ unsigned f2tf32(float x) {
    unsigned y;
    asm("cvt.rna.tf32.f32 %0, %1;" : "=r"(y) : "f"(x));
    return y;
}
__device__ __forceinline__ void mma_tf32(float d[4], const unsigned a[4],
                                         const unsigned b[2], const float c[4]) {
    asm volatile(
        "mma.sync.aligned.m16n8k8.row.col.f32.tf32.tf32.f32 "
        "{%0,%1,%2,%3}, {%4,%5,%6,%7}, {%8,%9}, {%10,%11,%12,%13};"
        : "=f"(d[0]), "=f"(d[1]), "=f"(d[2]), "=f"(d[3])
        : "r"(a[0]), "r"(a[1]), "r"(a[2]), "r"(a[3]),
          "r"(b[0]), "r"(b[1]),
          "f"(c[0]), "f"(c[1]), "f"(c[2]), "f"(c[3]));
}

// Generic tiled TF32 GEMM:
//   C[m,n] = epilogue( sum_k A(m,k) * B(k,n) )
// A(m,k) = A_K_CONTIG ? A[m*lda + k] : A[k*lda + m]
// B(k,n) = B_N_CONTIG ? B[k*ldb + n] : B[n*ldb + k]
// EPI==0: C += bias E[n];   EPI==1: C *= E[m]
// Requires M%128==0, N%128==0, K%16==0.
template<bool A_K_CONTIG, bool B_N_CONTIG, int EPI>
__launch_bounds__(256, 2)
__global__ void tgemm_kernel(const float* __restrict__ A,
                             const float* __restrict__ B,
                             const float* __restrict__ E,
                             float* __restrict__ C,
                             int M, int N, int K, int lda, int ldb)
{
    constexpr int ASZ = A_K_CONTIG ? BM * S_KC : BK * S_MC;
    constexpr int BSZ = B_N_CONTIG ? BK * S_MC : BN * S_KC;
    __shared__ float As[2][ASZ];
    __shared__ float Bs[2][BSZ];

    const int tid  = threadIdx.x;        // 0..255
    const int lane = tid & 31;
    const int warp = tid >> 5;           // 0..7
    const int wm   = warp >> 2;          // 0..1  (64 rows each)
    const int wn   = warp & 3;           // 0..3  (32 cols each)
    const int g    = lane >> 2;          // group 0..7
    const int t    = lane & 3;           // tig   0..3

    const int m0 = blockIdx.y * BM;
    const int n0 = blockIdx.x * BN;

    float acc[4][4][4];
#pragma unroll
    for (int i = 0; i < 4; i++)
#pragma unroll
        for (int j = 0; j < 4; j++)
#pragma unroll
            for (int r = 0; r < 4; r++) acc[i][j][r] = 0.f;

    // ---------------- async tile loaders ----------------
    auto load_tiles = [&](int stage, int k0) {
        // A panel
        if (A_K_CONTIG) {
            // gmem A[m][k] (k contig) -> As[m][S_KC]
            const int row = tid >> 1;            // 0..127
            const int cc  = (tid & 1) * 2;       // chunk 0 or 2 (of 4)
            const float* gp = &A[(size_t)(m0 + row) * lda + k0 + cc * 4];
            float* sp = &As[stage][row * S_KC + cc * 4];
            cp_async16(sp, gp);
            cp_async16(sp + 4, gp + 4);
        } else {
            // gmem A[k][m] (m contig) -> As[k][S_MC]
            const int row = tid >> 4;            // 0..15
            const int cc  = tid & 15;            // 0..15 (+16 second pass)
            const float* gp = &A[(size_t)(k0 + row) * lda + m0 + cc * 4];
            cp_async16(&As[stage][row * S_MC + cc * 4], gp);
            cp_async16(&As[stage][row * S_MC + (cc + 16) * 4], gp + 64);
        }
        // B panel
        if (B_N_CONTIG) {
            // gmem B[k][n] (n contig) -> Bs[k][S_MC]
            const int row = tid >> 4;
            const int cc  = tid & 15;
            const float* gp = &B[(size_t)(k0 + row) * ldb + n0 + cc * 4];
            cp_async16(&Bs[stage][row * S_MC + cc * 4], gp);
            cp_async16(&Bs[stage][row * S_MC + (cc + 16) * 4], gp + 64);
        } else {
            // gmem B[n][k] (k contig) -> Bs[n][S_KC]
            const int row = tid >> 1;
            const int cc  = (tid & 1) * 2;
            const float* gp = &B[(size_t)(n0 + row) * ldb + k0 + cc * 4];
            float* sp = &Bs[stage][row * S_KC + cc * 4];
            cp_async16(sp, gp);
            cp_async16(sp + 4, gp + 4);
        }
        cp_commit();
    };

    const int T = K / BK;
    load_tiles(0, 0);

    for (int kt = 0; kt < T; kt++) {
        if (kt + 1 < T) {
            load_tiles((kt + 1) & 1, (kt + 1) * BK);
        } else {
            cp_commit();   // empty group keeps wait<1> semantics uniform
        }
        cp_wait<1>();
        __syncthreads();

        const float* as = As[kt & 1];
        const float* bs = Bs[kt & 1];

#pragma unroll
        for (int ks = 0; ks < BK; ks += 8) {
            unsigned af[4][4];
#pragma unroll
            for (int mt = 0; mt < 4; mt++) {
                const int mrow = wm * 64 + mt * 16 + g;
                if (A_K_CONTIG) {
                    const int base = mrow * S_KC + ks;
                    af[mt][0] = f2tf32(as[base + t]);
                    af[mt][1] = f2tf32(as[base + 8 * S_KC + t]);
                    af[mt][2] = f2tf32(as[base + t + 4]);
                    af[mt][3] = f2tf32(as[base + 8 * S_KC + t + 4]);
                } else {
                    af[mt][0] = f2tf32(as[(ks + t) * S_MC + mrow]);
                    af[mt][1] = f2tf32(as[(ks + t) * S_MC + mrow + 8]);
                    af[mt][2] = f2tf32(as[(ks + t + 4) * S_MC + mrow]);
                    af[mt][3] = f2tf32(as[(ks + t + 4) * S_MC + mrow + 8]);
                }
            }
            unsigned bf[4][2];
#pragma unroll
            for (int nt = 0; nt < 4; nt++) {
                const int ncol = wn * 32 + nt * 8 + g;
                if (B_N_CONTIG) {
                    bf[nt][0] = f2tf32(bs[(ks + t) * S_MC + ncol]);
                    bf[nt][1] = f2tf32(bs[(ks + t + 4) * S_MC + ncol]);
                } else {
                    const int base = ncol * S_KC + ks;
                    bf[nt][0] = f2tf32(bs[base + t]);
                    bf[nt][1] = f2tf32(bs[base + t + 4]);
                }
            }
#pragma unroll
            for (int mt = 0; mt < 4; mt++)
#pragma unroll
                for (int nt = 0; nt < 4; nt++)
                    mma_tf32(acc[mt][nt], af[mt], bf[nt], acc[mt][nt]);
        }
        __syncthreads();
    }

    // ---------------- epilogue + store ----------------
    // c0:(g, 2t), c1:(g, 2t+1), c2:(g+8, 2t), c3:(g+8, 2t+1)
#pragma unroll
    for (int mt = 0; mt < 4; mt++) {
        const int mrow0 = m0 + wm * 64 + mt * 16 + g;
        const int mrow1 = mrow0 + 8;
        float s0 = 1.f, s1 = 1.f;
        if (EPI == 1) { s0 = E[mrow0]; s1 = E[mrow1]; }
#pragma unroll
        for (int nt = 0; nt < 4; nt++) {
            const int ncol = n0 + wn * 32 + nt * 8 + 2 * t;
            float2 v0, v1;
            v0.x = acc[mt][nt][0]; v0.y = acc[mt][nt][1];
            v1.x = acc[mt][nt][2]; v1.y = acc[mt][nt][3];
            if (EPI == 0) {
                const float2 bias = *reinterpret_cast<const float2*>(&E[ncol]);
                v0.x += bias.x; v0.y += bias.y;
                v1.x += bias.x; v1.y += bias.y;
            } else {
                v0.x *= s0; v0.y *= s0;
                v1.x *= s1; v1.y *= s1;
            }
            *reinterpret_cast<float2*>(&C[(size_t)mrow0 * N + ncol]) = v0;
            *reinterpret_cast<float2*>(&C[(size_t)mrow1 * N + ncol]) = v1;
        }
    }
}

extern "C" void kernel_launch(void* const* d_in, const int* in_sizes, int n_in,
                              void* d_out, int out_size)
{
    const float* input  = (const float*)d_in[0];  // (N_TOT, D_IN)
    const float* adj    = (const float*)d_in[1];  // (N_U, N_I)
    const float* degree = (const float*)d_in[2];  // (N_TOT,)
    const float* W      = (const float*)d_in[3];  // (D_H, D_IN)
    const float* b      = (const float*)d_in[4];  // (D_H,)
    float* out = (float*)d_out;                   // (N_TOT, D_H)

    float* support = nullptr;
    cudaGetSymbolAddress((void**)&support, g_support);

    const float* sup_u = support;                       // rows [0, N_U)
    const float* sup_i = support + (size_t)N_U * D_H;   // rows [N_U, N_TOT)

    dim3 blk(256);

    // GEMM1: support = input @ W^T + b
    // A = input (K-contig); B(k,n) = W[n*D_IN + k] (K-contig -> B_N_CONTIG=false)
    {
        dim3 grid(D_H / BN, N_TOT / BM);
        tgemm_kernel<true, false, 0><<<grid, blk>>>(
            input, W, b, support, N_TOT, D_H, D_IN, D_IN, D_IN);
    }
    // GEMM2: out_u = deg_u ⊙ (adj @ sup_i)
    {
        dim3 grid(D_H / BN, N_U / BM);
        tgemm_kernel<true, true, 1><<<grid, blk>>>(
            adj, sup_i, degree, out, N_U, D_H, N_I, N_I, D_H);
    }
    // GEMM3: out_i = deg_i ⊙ (adj^T @ sup_u)
    // A(m,k) = adj[k*N_I + m] (m contiguous -> A_K_CONTIG=false)
    {
        dim3 grid(D_H / BN, N_I / BM);
        tgemm_kernel<false, true, 1><<<grid, blk>>>(
            adj, sup_u, degree + N_U, out + (size_t)N_U * D_H,
            N_I, D_H, N_U, N_I, D_H);
    }
}

// round 4
// speedup vs baseline: 6.5790x; 2.2439x over previous
#include <cuda_runtime.h>
#include <cuda_fp16.h>
#include <cstdint>
#include <cstddef>

// ---------------- problem constants ----------------
#define N_Uc   8192
#define N_Ic   8192
#define D_INc  2048
#define D_Hc   2048
#define N_TOTc (N_Uc + N_Ic)

// ---------------- fp16 scratch (device globals; no allocs allowed) ----------------
__device__ __half g_inputH[(size_t)N_TOTc * D_INc];   // rn(input)  [16384][2048]
__device__ __half g_WH[(size_t)D_Hc * D_INc];         // rn(W)      [2048][2048]
__device__ __half g_adjH[(size_t)N_Uc * N_Ic];        // rn(adj)    [8192][8192]
__device__ __half g_supH[(size_t)N_TOTc * D_Hc];      // rn(support)[16384][2048]

// ---------------- PTX helpers ----------------
__device__ __forceinline__ uint32_t smem_u32(const void* p) {
    uint32_t a;
    asm("{ .reg .u64 t; cvta.to.shared.u64 t, %1; cvt.u32.u64 %0, t; }" : "=r"(a) : "l"(p));
    return a;
}
__device__ __forceinline__ void cp_async16(uint32_t s, const void* g) {
    asm volatile("cp.async.cg.shared.global [%0], [%1], 16;" :: "r"(s), "l"(g));
}
__device__ __forceinline__ void cp_commit() {
    asm volatile("cp.async.commit_group;" ::: "memory");
}
template<int N>
__device__ __forceinline__ void cp_wait() {
    asm volatile("cp.async.wait_group %0;" :: "n"(N) : "memory");
}
__device__ __forceinline__ void ldsm_x4(uint32_t& r0, uint32_t& r1, uint32_t& r2,
                                        uint32_t& r3, uint32_t addr) {
    asm volatile("ldmatrix.sync.aligned.m8n8.x4.shared.b16 {%0,%1,%2,%3}, [%4];"
                 : "=r"(r0), "=r"(r1), "=r"(r2), "=r"(r3) : "r"(addr));
}
__device__ __forceinline__ void ldsm_x4_t(uint32_t& r0, uint32_t& r1, uint32_t& r2,
                                          uint32_t& r3, uint32_t addr) {
    asm volatile("ldmatrix.sync.aligned.m8n8.x4.trans.shared.b16 {%0,%1,%2,%3}, [%4];"
                 : "=r"(r0), "=r"(r1), "=r"(r2), "=r"(r3) : "r"(addr));
}
__device__ __forceinline__ void mma_f16(float d[4], const uint32_t a[4],
                                        const uint32_t b[2], const float c[4]) {
    asm volatile(
        "mma.sync.aligned.m16n8k16.row.col.f32.f16.f16.f32 "
        "{%0,%1,%2,%3}, {%4,%5,%6,%7}, {%8,%9}, {%10,%11,%12,%13};"
        : "=f"(d[0]), "=f"(d[1]), "=f"(d[2]), "=f"(d[3])
        : "r"(a[0]), "r"(a[1]), "r"(a[2]), "r"(a[3]),
          "r"(b[0]), "r"(b[1]),
          "f"(c[0]), "f"(c[1]), "f"(c[2]), "f"(c[3]));
}

// ---------------- GEMM ----------------
//   C[m][n] = epi( sum_k A(m,k)*B(k,n) )
// A(m,k) = A_K_CONTIG ? A[m*lda+k] : A[k*lda+m]   (halves)
// B(k,n) = B_N_CONTIG ? B[k*ldb+n] : B[n*ldb+k]   (halves)
// EPI==0: C (half) [m][ldc] = rn(acc + E[n])      (bias; writes fp16 support)
// EPI==1: C (float)[m][ldc] = acc * E[m]          (degree scale)
#define BMh 128
#define BNh 128
#define BKh 32
// smem panel strides (bytes): K-contig rows (32 halves) padded 64->80B;
// MN-contig rows (128 halves) padded 256->272B. Both conflict-free for ldmatrix.
#define SKC 80
#define SMC 272

template<bool A_K_CONTIG, bool B_N_CONTIG, int EPI>
__launch_bounds__(256, 2)
__global__ void hgemm(const __half* __restrict__ A, const __half* __restrict__ B,
                      const float* __restrict__ E, void* __restrict__ Cv,
                      int N, int K, int lda, int ldb, int ldc)
{
    constexpr int ASZ = A_K_CONTIG ? BMh * SKC : BKh * SMC;   // bytes
    constexpr int BSZ = B_N_CONTIG ? BKh * SMC : BNh * SKC;
    __shared__ __align__(16) char smem[2 * (ASZ + BSZ)];
    const uint32_t sb = smem_u32(smem);

    const int tid  = threadIdx.x;
    const int lane = tid & 31;
    const int warp = tid >> 5;
    const int wm   = warp >> 2;          // 0..1  (64 rows)
    const int wn   = warp & 3;           // 0..3  (32 cols)
    const int q    = lane >> 3;          // ldmatrix quad 0..3
    const int r    = lane & 7;
    const int g    = lane >> 2;
    const int t    = lane & 3;

    const int m0 = blockIdx.y * BMh;
    const int n0 = blockIdx.x * BNh;

    float acc[4][4][4];
#pragma unroll
    for (int i = 0; i < 4; i++)
#pragma unroll
        for (int j = 0; j < 4; j++)
#pragma unroll
            for (int k = 0; k < 4; k++) acc[i][j][k] = 0.f;

    // -------- per-thread ldmatrix base offsets (bytes, within panel) --------
    uint32_t a_base, b_base;
    if (A_K_CONTIG)   // matrices: q0:(m r, k lo) q1:(m r+8, k lo) q2:(m r, k hi) q3:(m r+8, k hi)
        a_base = (uint32_t)((wm * 64 + r + (q & 1) * 8) * SKC + (q >> 1) * 16);
    else              // trans; rows are k: q0:(k lo, m lo) q1:(k lo, m hi) q2:(k hi, m lo) q3:(k hi, m hi)
        a_base = (uint32_t)((r + (q >> 1) * 8) * SMC + (wm * 64 + (q & 1) * 8) * 2);
    if (B_N_CONTIG)   // trans; q0:(k lo, n lo) q1:(k hi, n lo) q2:(k lo, n hi) q3:(k hi, n hi)
        b_base = (uint32_t)((r + (q & 1) * 8) * SMC + (wn * 32 + (q >> 1) * 8) * 2);
    else              // W layout [n][k]; q0:(n lo, k lo) q1:(n lo, k hi) q2:(n hi, k lo) q3:(n hi, k hi)
        b_base = (uint32_t)((wn * 32 + r + (q >> 1) * 8) * SKC + (q & 1) * 16);

    // -------- stage fill (cp.async, 16B chunks) --------
    auto fill = [&](int s, int kt) {
        const uint32_t ab = sb + (uint32_t)s * (ASZ + BSZ);
        const uint32_t bb = ab + ASZ;
        const int k0 = kt * BKh;
        if (A_K_CONTIG) {   // 128 rows x 4 chunks
#pragma unroll
            for (int i = 0; i < 2; i++) {
                int ci = tid + i * 256, row = ci >> 2, c = ci & 3;
                cp_async16(ab + row * SKC + c * 16,
                           A + (size_t)(m0 + row) * lda + k0 + c * 8);
            }
        } else {            // 32 k-rows x 16 chunks
#pragma unroll
            for (int i = 0; i < 2; i++) {
                int ci = tid + i * 256, row = ci >> 4, c = ci & 15;
                cp_async16(ab + row * SMC + c * 16,
                           A + (size_t)(k0 + row) * lda + m0 + c * 8);
            }
        }
        if (B_N_CONTIG) {   // 32 k-rows x 16 chunks
#pragma unroll
            for (int i = 0; i < 2; i++) {
                int ci = tid + i * 256, row = ci >> 4, c = ci & 15;
                cp_async16(bb + row * SMC + c * 16,
                           B + (size_t)(k0 + row) * ldb + n0 + c * 8);
            }
        } else {            // 128 n-rows x 4 chunks
#pragma unroll
            for (int i = 0; i < 2; i++) {
                int ci = tid + i * 256, row = ci >> 2, c = ci & 3;
                cp_async16(bb + row * SKC + c * 16,
                           B + (size_t)(n0 + row) * ldb + k0 + c * 8);
            }
        }
        cp_commit();
    };

    const int T = K / BKh;
    fill(0, 0);

    for (int kt = 0; kt < T; kt++) {
        if (kt + 1 < T) fill((kt + 1) & 1, kt + 1);
        else            cp_commit();
        cp_wait<1>();
        __syncthreads();

        const uint32_t ab = sb + (uint32_t)(kt & 1) * (ASZ + BSZ);
        const uint32_t bb = ab + ASZ;
        const uint32_t aa = ab + a_base;
        const uint32_t ba = bb + b_base;

#pragma unroll
        for (int ks = 0; ks < 2; ks++) {   // two k16 steps per stage
            const uint32_t ak = A_K_CONTIG ? (aa + ks * 32) : (aa + ks * 16 * SMC);
            const uint32_t bk = B_N_CONTIG ? (ba + ks * 16 * SMC) : (ba + ks * 32);

            uint32_t af[4][4];
#pragma unroll
            for (int mt = 0; mt < 4; mt++) {
                const uint32_t addr = A_K_CONTIG ? (ak + mt * 16 * SKC) : (ak + mt * 32);
                if (A_K_CONTIG) ldsm_x4  (af[mt][0], af[mt][1], af[mt][2], af[mt][3], addr);
                else            ldsm_x4_t(af[mt][0], af[mt][1], af[mt][2], af[mt][3], addr);
            }
            uint32_t bf[4][2];
#pragma unroll
            for (int h = 0; h < 2; h++) {  // 2 x4 loads cover 4 n-tiles
                const uint32_t addr = B_N_CONTIG ? (bk + h * 32) : (bk + h * 16 * SKC);
                if (B_N_CONTIG) ldsm_x4_t(bf[2*h][0], bf[2*h][1], bf[2*h+1][0], bf[2*h+1][1], addr);
                else            ldsm_x4  (bf[2*h][0], bf[2*h][1], bf[2*h+1][0], bf[2*h+1][1], addr);
            }
#pragma unroll
            for (int mt = 0; mt < 4; mt++)
#pragma unroll
                for (int nt = 0; nt < 4; nt++)
                    mma_f16(acc[mt][nt], af[mt], bf[nt], acc[mt][nt]);
        }
        __syncthreads();
    }

    // -------- epilogue --------
#pragma unroll
    for (int mt = 0; mt < 4; mt++) {
        const int mr0 = m0 + wm * 64 + mt * 16 + g;
        const int mr1 = mr0 + 8;
        float s0 = 1.f, s1 = 1.f;
        if (EPI == 1) { s0 = E[mr0]; s1 = E[mr1]; }
#pragma unroll
        for (int nt = 0; nt < 4; nt++) {
            const int nc = n0 + wn * 32 + nt * 8 + 2 * t;
            if (EPI == 0) {
                __half* C = (__half*)Cv;
                const float bx = E[nc], by = E[nc + 1];
                *reinterpret_cast<__half2*>(&C[(size_t)mr0 * ldc + nc]) =
                    __floats2half2_rn(acc[mt][nt][0] + bx, acc[mt][nt][1] + by);
                *reinterpret_cast<__half2*>(&C[(size_t)mr1 * ldc + nc]) =
                    __floats2half2_rn(acc[mt][nt][2] + bx, acc[mt][nt][3] + by);
            } else {
                float* C = (float*)Cv;
                float2 v0 = make_float2(acc[mt][nt][0] * s0, acc[mt][nt][1] * s0);
                float2 v1 = make_float2(acc[mt][nt][2] * s1, acc[mt][nt][3] * s1);
                *reinterpret_cast<float2*>(&C[(size_t)mr0 * ldc + nc]) = v0;
                *reinterpret_cast<float2*>(&C[(size_t)mr1 * ldc + nc]) = v1;
            }
        }
    }
}

// ---------------- fp32 -> fp16 pre-pass ----------------
__global__ void f32_to_f16(const float* __restrict__ src, __half* __restrict__ dst) {
    size_t i = ((size_t)blockIdx.x * blockDim.x + threadIdx.x) * 8;
    float4 v0 = *reinterpret_cast<const float4*>(src + i);
    float4 v1 = *reinterpret_cast<const float4*>(src + i + 4);
    __half2 h0 = __floats2half2_rn(v0.x, v0.y);
    __half2 h1 = __floats2half2_rn(v0.z, v0.w);
    __half2 h2 = __floats2half2_rn(v1.x, v1.y);
    __half2 h3 = __floats2half2_rn(v1.z, v1.w);
    uint4 u;
    u.x = *reinterpret_cast<uint32_t*>(&h0);
    u.y = *reinterpret_cast<uint32_t*>(&h1);
    u.z = *reinterpret_cast<uint32_t*>(&h2);
    u.w = *reinterpret_cast<uint32_t*>(&h3);
    *reinterpret_cast<uint4*>(dst + i) = u;
}

// ---------------- launch ----------------
extern "C" void kernel_launch(void* const* d_in, const int* in_sizes, int n_in,
                              void* d_out, int out_size)
{
    const float* input  = (const float*)d_in[0];
    const float* adj    = (const float*)d_in[1];
    const float* degree = (const float*)d_in[2];
    const float* W      = (const float*)d_in[3];
    const float* b      = (const float*)d_in[4];
    float* out = (float*)d_out;

    __half *inputH, *WH, *adjH, *supH;
    cudaGetSymbolAddress((void**)&inputH, g_inputH);
    cudaGetSymbolAddress((void**)&WH, g_WH);
    cudaGetSymbolAddress((void**)&adjH, g_adjH);
    cudaGetSymbolAddress((void**)&supH, g_supH);

    // pre-passes: RN-round everything to fp16 once (removes all in-loop cvt)
    f32_to_f16<<<(size_t)N_TOTc * D_INc / (8 * 256), 256>>>(input, inputH);
    f32_to_f16<<<(size_t)D_Hc * D_INc / (8 * 256), 256>>>(W, WH);
    f32_to_f16<<<(size_t)N_Uc * N_Ic / (8 * 256), 256>>>(adj, adjH);

    // GEMM1: supH = rn( input @ W^T + b )  (M=16384, N=2048, K=2048)
    // A=inputH K-contig; B=WH [n][k] K-contig
    {
        dim3 grid(D_Hc / BNh, N_TOTc / BMh);
        hgemm<true, false, 0><<<grid, 256>>>(
            inputH, WH, b, supH, D_Hc, D_INc, D_INc, D_INc, D_Hc);
    }
    // GEMM2: out_u = deg_u * (adj @ sup_i)   A=adjH K-contig; B=supH[N_U:] [k][n] N-contig
    {
        dim3 grid(D_Hc / BNh, N_Uc / BMh);
        hgemm<true, true, 1><<<grid, 256>>>(
            adjH, supH + (size_t)N_Uc * D_Hc, degree, out,
            D_Hc, N_Ic, N_Ic, D_Hc, D_Hc);
    }
    // GEMM3: out_i = deg_i * (adj^T @ sup_u)  A=adjH read [k][m] (M-contig); B=supH[:N_U]
    {
        dim3 grid(D_Hc / BNh, N_Ic / BMh);
        hgemm<false, true, 1><<<grid, 256>>>(
            adjH, supH, degree + N_Uc, out + (size_t)N_Uc * D_Hc,
            D_Hc, N_Uc, N_Ic, D_Hc, D_Hc);
    }
}